// round 14
// baseline (speedup 1.0000x reference)
#include <cuda_runtime.h>
#include <cuda_bf16.h>
#include <math_constants.h>

// out = x * (1 + sigmoid(max_{h,w} x)) per (b,c) plane; x: (32,512,56,56) fp32.
// (The reference's two channel shuffles are inverse permutations, so the gate
// is just sigmoid of the per-plane spatial max.)
//
// Warp-per-plane, barrier-free: each warp owns one 3136-float plane
// (784 float4 = 24 per lane + 16-lane tail). Pass 1 streams the plane
// (warming L1) with a lane-local running max; 5 shuffle-xor steps give every
// lane the plane max; every lane computes the scale redundantly (no smem, no
// __syncthreads). Pass 2 reloads the L1-resident plane, scales, stores.
// With zero CTA-wide barriers the 8 warps per CTA are independent memory
// streams, so the SM always has warps in load phase and the DRAM queue never
// collectively drains (the phase-lock bubble that capped round 12 at 79.5%).

#define HW4 784            // 56*56/4 float4 per plane
#define THREADS 256
#define WARPS_PER_CTA 8

__global__ __launch_bounds__(THREADS, 6)
void dca_warp_kernel(const float4* __restrict__ x4,
                     float4* __restrict__ o4,
                     int planes) {
    const int lane = threadIdx.x & 31;
    const int plane = blockIdx.x * WARPS_PER_CTA + (threadIdx.x >> 5);
    if (plane >= planes) return;

    const float4* __restrict__ xin  = x4 + (size_t)plane * HW4;
    float4*       __restrict__ xout = o4 + (size_t)plane * HW4;

    // ---- pass 1: stream plane, lane-local max (loads warm L1) ----
    float m = -CUDART_INF_F;
    #pragma unroll
    for (int i = 0; i < 24; i++) {
        float4 v = xin[lane + 32 * i];
        m = fmaxf(m, fmaxf(fmaxf(v.x, v.y), fmaxf(v.z, v.w)));
    }
    if (lane < 16) {
        float4 v = xin[lane + 768];
        m = fmaxf(m, fmaxf(fmaxf(v.x, v.y), fmaxf(v.z, v.w)));
    }

    // ---- warp max reduce; all lanes end up with the plane max ----
    #pragma unroll
    for (int o = 16; o > 0; o >>= 1)
        m = fmaxf(m, __shfl_xor_sync(0xffffffffu, m, o));

    // gate = sigmoid(m); multiplier = 1 + gate  (computed in every lane)
    const float s = 1.0f + 1.0f / (1.0f + __expf(-m));

    // ---- pass 2: reload (L1-resident), scale, store ----
    #pragma unroll
    for (int i = 0; i < 24; i++) {
        float4 v = xin[lane + 32 * i];
        v.x *= s; v.y *= s; v.z *= s; v.w *= s;
        xout[lane + 32 * i] = v;
    }
    if (lane < 16) {
        float4 v = xin[lane + 768];
        v.x *= s; v.y *= s; v.z *= s; v.w *= s;
        xout[lane + 768] = v;
    }
}

extern "C" void kernel_launch(void* const* d_in, const int* in_sizes, int n_in,
                              void* d_out, int out_size) {
    const float4* x4 = (const float4*)d_in[0];
    float4* o4 = (float4*)d_out;
    const int planes = in_sizes[0] / (HW4 * 4);             // 16384 here
    const int grid = (planes + WARPS_PER_CTA - 1) / WARPS_PER_CTA;  // 2048
    dca_warp_kernel<<<grid, THREADS>>>(x4, o4, planes);
}

// round 15
// speedup vs baseline: 2.0080x; 2.0080x over previous
#include <cuda_runtime.h>
#include <cuda_bf16.h>
#include <math_constants.h>

// out = x * (1 + sigmoid(max_{h,w} x)) per (b,c) plane; x: (32,512,56,56) fp32.
// (Reference's two channel shuffles are inverse permutations -> gate is just
// sigmoid of the per-plane spatial max.)
//
// Round-12 winning structure (one 256-thread CTA per 3136-float plane,
// classic 16384-CTA launch) with micro-fixes:
//  - all 4 float4 loads per thread are unconditional & front-batched
//    (4th uses a clamped index; duplicate value is idempotent under max)
//  - single __syncthreads(): every thread folds the 8 per-warp maxima from
//    smem itself (broadcast LDS) instead of a second barrier + broadcast.

#define HW4 784        // 56*56/4 float4 per plane
#define THREADS 256

__global__ __launch_bounds__(THREADS)
void dca_fused_kernel(const float4* __restrict__ x4, float4* __restrict__ o4) {
    const size_t base = (size_t)blockIdx.x * HW4;
    const float4* __restrict__ xin  = x4 + base;
    float4*       __restrict__ xout = o4 + base;

    const int tid  = threadIdx.x;
    const int lane = tid & 31;
    const int wid  = tid >> 5;

    // clamped 4th index: tid<16 -> tid+768 (769..783), else 783 (dup, harmless)
    const int i3 = (tid < HW4 - 768) ? (tid + 768) : (HW4 - 1);

    // ---- front-batched loads (MLP_p1 = 4) ----
    float4 v0 = xin[tid];
    float4 v1 = xin[tid + 256];
    float4 v2 = xin[tid + 512];
    float4 v3 = xin[i3];

    float m = fmaxf(fmaxf(v0.x, v0.y), fmaxf(v0.z, v0.w));
    m = fmaxf(m, fmaxf(fmaxf(v1.x, v1.y), fmaxf(v1.z, v1.w)));
    m = fmaxf(m, fmaxf(fmaxf(v2.x, v2.y), fmaxf(v2.z, v2.w)));
    m = fmaxf(m, fmaxf(fmaxf(v3.x, v3.y), fmaxf(v3.z, v3.w)));

    // ---- warp max reduce ----
    #pragma unroll
    for (int o = 16; o > 0; o >>= 1)
        m = fmaxf(m, __shfl_xor_sync(0xffffffffu, m, o));

    __shared__ float wmax[8];
    if (lane == 0) wmax[wid] = m;
    __syncthreads();

    // ---- every thread folds the 8 warp maxima (broadcast LDS, no 2nd bar) ----
    float t = wmax[0];
    #pragma unroll
    for (int i = 1; i < 8; i++) t = fmaxf(t, wmax[i]);

    // multiplier = 1 + sigmoid(t)
    const float s = 1.0f + 1.0f / (1.0f + __expf(-t));

    // ---- scale + store (reload from L1 is fine if ptxas remats) ----
    v0.x *= s; v0.y *= s; v0.z *= s; v0.w *= s;
    v1.x *= s; v1.y *= s; v1.z *= s; v1.w *= s;
    v2.x *= s; v2.y *= s; v2.z *= s; v2.w *= s;

    xout[tid]       = v0;
    xout[tid + 256] = v1;
    xout[tid + 512] = v2;
    if (tid < HW4 - 768) {
        v3.x *= s; v3.y *= s; v3.z *= s; v3.w *= s;
        xout[tid + 768] = v3;
    }
}

extern "C" void kernel_launch(void* const* d_in, const int* in_sizes, int n_in,
                              void* d_out, int out_size) {
    const float4* x4 = (const float4*)d_in[0];
    float4* o4 = (float4*)d_out;
    const int planes = in_sizes[0] / (HW4 * 4);   // 16384 for this shape
    dca_fused_kernel<<<planes, THREADS>>>(x4, o4);
}

// round 16
// speedup vs baseline: 2.0100x; 1.0010x over previous
#include <cuda_runtime.h>
#include <cuda_bf16.h>
#include <math_constants.h>

// out = x * (1 + sigmoid(max_{h,w} x)) per (b,c) plane; x: (32,512,56,56) fp32.
// (Reference's two channel shuffles are inverse permutations -> gate is just
// sigmoid of the per-plane spatial max.)
//
// One 128-thread CTA per 3136-float plane (784 float4 = 6 per thread + 16 tail).
// vs round 15 (256 thr): 16 CTAs/SM instead of 8 -> 2x independent memory
// streams per SM, and 7 front-batched LDG.128 per thread instead of 4 ->
// deeper DRAM queue through each CTA's reduce/barrier window.
// Loads 0..5 unconditional; load 6 uses a clamped index (duplicate of the last
// element for tid>=16 — idempotent under max). Stores use evict-first (.cs)
// since output lines are never re-read.

#define HW4 784        // 56*56/4 float4 per plane
#define THREADS 128

__global__ __launch_bounds__(THREADS)
void dca_fused_kernel(const float4* __restrict__ x4, float4* __restrict__ o4) {
    const size_t base = (size_t)blockIdx.x * HW4;
    const float4* __restrict__ xin  = x4 + base;
    float4*       __restrict__ xout = o4 + base;

    const int tid  = threadIdx.x;
    const int lane = tid & 31;
    const int wid  = tid >> 5;

    // clamped 7th index: tid<16 -> tid+768 (769..783), else 783 (dup, harmless)
    const int i6 = (tid < HW4 - 768) ? (tid + 768) : (HW4 - 1);

    // ---- front-batched loads (7 LDG.128 in flight per thread) ----
    float4 v0 = xin[tid];
    float4 v1 = xin[tid + 128];
    float4 v2 = xin[tid + 256];
    float4 v3 = xin[tid + 384];
    float4 v4 = xin[tid + 512];
    float4 v5 = xin[tid + 640];
    float4 v6 = xin[i6];

    float m;
    m = fmaxf(fmaxf(v0.x, v0.y), fmaxf(v0.z, v0.w));
    m = fmaxf(m, fmaxf(fmaxf(v1.x, v1.y), fmaxf(v1.z, v1.w)));
    m = fmaxf(m, fmaxf(fmaxf(v2.x, v2.y), fmaxf(v2.z, v2.w)));
    m = fmaxf(m, fmaxf(fmaxf(v3.x, v3.y), fmaxf(v3.z, v3.w)));
    m = fmaxf(m, fmaxf(fmaxf(v4.x, v4.y), fmaxf(v4.z, v4.w)));
    m = fmaxf(m, fmaxf(fmaxf(v5.x, v5.y), fmaxf(v5.z, v5.w)));
    m = fmaxf(m, fmaxf(fmaxf(v6.x, v6.y), fmaxf(v6.z, v6.w)));

    // ---- warp max reduce ----
    #pragma unroll
    for (int o = 16; o > 0; o >>= 1)
        m = fmaxf(m, __shfl_xor_sync(0xffffffffu, m, o));

    __shared__ float wmax[4];
    if (lane == 0) wmax[wid] = m;
    __syncthreads();

    // ---- every thread folds the 4 warp maxima (broadcast LDS, 1 barrier) ----
    float t = fmaxf(fmaxf(wmax[0], wmax[1]), fmaxf(wmax[2], wmax[3]));

    // multiplier = 1 + sigmoid(t)
    const float s = 1.0f + 1.0f / (1.0f + __expf(-t));

    // ---- scale + store (evict-first: never re-read) ----
    v0.x *= s; v0.y *= s; v0.z *= s; v0.w *= s;
    v1.x *= s; v1.y *= s; v1.z *= s; v1.w *= s;
    v2.x *= s; v2.y *= s; v2.z *= s; v2.w *= s;
    v3.x *= s; v3.y *= s; v3.z *= s; v3.w *= s;
    v4.x *= s; v4.y *= s; v4.z *= s; v4.w *= s;
    v5.x *= s; v5.y *= s; v5.z *= s; v5.w *= s;

    __stcs(xout + tid,       v0);
    __stcs(xout + tid + 128, v1);
    __stcs(xout + tid + 256, v2);
    __stcs(xout + tid + 384, v3);
    __stcs(xout + tid + 512, v4);
    __stcs(xout + tid + 640, v5);
    if (tid < HW4 - 768) {
        v6.x *= s; v6.y *= s; v6.z *= s; v6.w *= s;
        __stcs(xout + tid + 768, v6);
    }
}

extern "C" void kernel_launch(void* const* d_in, const int* in_sizes, int n_in,
                              void* d_out, int out_size) {
    const float4* x4 = (const float4*)d_in[0];
    float4* o4 = (float4*)d_out;
    const int planes = in_sizes[0] / (HW4 * 4);   // 16384 for this shape
    dca_fused_kernel<<<planes, THREADS>>>(x4, o4);
}

// round 17
// speedup vs baseline: 2.0170x; 1.0035x over previous
#include <cuda_runtime.h>
#include <cuda_bf16.h>
#include <math_constants.h>

// out = x * (1 + sigmoid(max_{h,w} x)) per (b,c) plane; x: (32,512,56,56) fp32.
// (Reference's two channel shuffles are inverse permutations -> gate is just
// sigmoid of the per-plane spatial max.)
//
// Best-known structure (round 15): one 256-thread CTA per 3136-float plane,
// classic 16384-CTA launch, 4 front-batched float4 loads per thread, warp
// shuffle reduce + single __syncthreads + broadcast-LDS fold.
// New in this round (isolated knob): evict-first (__stcs) stores — output
// lines are never re-read, so keep them from displacing the inbound read
// stream in L2.

#define HW4 784        // 56*56/4 float4 per plane
#define THREADS 256

__global__ __launch_bounds__(THREADS)
void dca_fused_kernel(const float4* __restrict__ x4, float4* __restrict__ o4) {
    const size_t base = (size_t)blockIdx.x * HW4;
    const float4* __restrict__ xin  = x4 + base;
    float4*       __restrict__ xout = o4 + base;

    const int tid  = threadIdx.x;
    const int lane = tid & 31;
    const int wid  = tid >> 5;

    // clamped 4th index: tid<16 -> tid+768 (769..783), else 783 (dup, harmless)
    const int i3 = (tid < HW4 - 768) ? (tid + 768) : (HW4 - 1);

    // ---- front-batched loads ----
    float4 v0 = xin[tid];
    float4 v1 = xin[tid + 256];
    float4 v2 = xin[tid + 512];
    float4 v3 = xin[i3];

    float m = fmaxf(fmaxf(v0.x, v0.y), fmaxf(v0.z, v0.w));
    m = fmaxf(m, fmaxf(fmaxf(v1.x, v1.y), fmaxf(v1.z, v1.w)));
    m = fmaxf(m, fmaxf(fmaxf(v2.x, v2.y), fmaxf(v2.z, v2.w)));
    m = fmaxf(m, fmaxf(fmaxf(v3.x, v3.y), fmaxf(v3.z, v3.w)));

    // ---- warp max reduce ----
    #pragma unroll
    for (int o = 16; o > 0; o >>= 1)
        m = fmaxf(m, __shfl_xor_sync(0xffffffffu, m, o));

    __shared__ float wmax[8];
    if (lane == 0) wmax[wid] = m;
    __syncthreads();

    // ---- every thread folds the 8 warp maxima (broadcast LDS, 1 barrier) ----
    float t = wmax[0];
    #pragma unroll
    for (int i = 1; i < 8; i++) t = fmaxf(t, wmax[i]);

    // multiplier = 1 + sigmoid(t)
    const float s = 1.0f + 1.0f / (1.0f + __expf(-t));

    // ---- scale + evict-first store (output never re-read) ----
    v0.x *= s; v0.y *= s; v0.z *= s; v0.w *= s;
    v1.x *= s; v1.y *= s; v1.z *= s; v1.w *= s;
    v2.x *= s; v2.y *= s; v2.z *= s; v2.w *= s;

    __stcs(xout + tid,       v0);
    __stcs(xout + tid + 256, v1);
    __stcs(xout + tid + 512, v2);
    if (tid < HW4 - 768) {
        v3.x *= s; v3.y *= s; v3.z *= s; v3.w *= s;
        __stcs(xout + tid + 768, v3);
    }
}

extern "C" void kernel_launch(void* const* d_in, const int* in_sizes, int n_in,
                              void* d_out, int out_size) {
    const float4* x4 = (const float4*)d_in[0];
    float4* o4 = (float4*)d_out;
    const int planes = in_sizes[0] / (HW4 * 4);   // 16384 for this shape
    dca_fused_kernel<<<planes, THREADS>>>(x4, o4);
}